// round 2
// baseline (speedup 1.0000x reference)
#include <cuda_runtime.h>
#include <stdint.h>

// Shapes (fixed by the problem)
#define B_  32
#define S_  4096
#define H_  2048
#define ADAPT_ 32
#define RANK_ 16
#define K_ 8

#define SSPLIT 64              // S chunks of 64 rows each
#define ROWS_PER (S_ / SSPLIT) // 64

// Static scratch (no allocations allowed)
__device__ float g_scratch[SSPLIT * B_ * H_];   // 16 MB partial sums
__device__ float g_hpre[B_ * ADAPT_];           // pre-LN adaptation features

// ---------------------------------------------------------------------------
// Pass 1: partial column sums of hidden_states over S chunks.
// grid (SSPLIT, B_), block 512. Each thread owns one float4 (4 H-columns).
// ---------------------------------------------------------------------------
__global__ __launch_bounds__(512) void pass1_partial_sums(const float* __restrict__ x) {
    const int split = blockIdx.x;
    const int b     = blockIdx.y;
    const int t     = threadIdx.x;  // 0..511, 512*4 = 2048 = H_

    const float4* p = reinterpret_cast<const float4*>(x)
                    + ((size_t)b * S_ + (size_t)split * ROWS_PER) * (H_ / 4) + t;

    float ax = 0.f, ay = 0.f, az = 0.f, aw = 0.f;
#pragma unroll 8
    for (int s = 0; s < ROWS_PER; ++s) {
        float4 v = p[(size_t)s * (H_ / 4)];
        ax += v.x; ay += v.y; az += v.z; aw += v.w;
    }
    float4 out = make_float4(ax, ay, az, aw);
    reinterpret_cast<float4*>(g_scratch)[((size_t)split * B_ + b) * (H_ / 4) + t] = out;
}

// ---------------------------------------------------------------------------
// Pass 2: per-batch final reduce -> pooled row (smem) -> pooled @ W1 + b1.
// grid B_, block 256.
// ---------------------------------------------------------------------------
__global__ __launch_bounds__(256) void pass2_pool_proj(const float* __restrict__ W1,
                                                       const float* __restrict__ b1) {
    const int b   = blockIdx.x;
    const int tid = threadIdx.x;

    __shared__ __align__(16) float pooled[H_];

    // reduce 64 partials; each thread handles 2 float4 columns
    for (int c = tid; c < H_ / 4; c += 256) {
        float ax = 0.f, ay = 0.f, az = 0.f, aw = 0.f;
#pragma unroll 8
        for (int k = 0; k < SSPLIT; ++k) {
            float4 v = reinterpret_cast<const float4*>(g_scratch)[((size_t)k * B_ + b) * (H_ / 4) + c];
            ax += v.x; ay += v.y; az += v.z; aw += v.w;
        }
        const float inv = 1.0f / (float)S_;
        float4 o = make_float4(ax * inv, ay * inv, az * inv, aw * inv);
        reinterpret_cast<float4*>(pooled)[c] = o;
    }
    __syncthreads();

    // proj[a] = sum_h pooled[h] * W1[h,a];  8 groups of 32 threads
    const int a = tid & 31;
    const int g = tid >> 5;
    const int h0 = g * (H_ / 8);
    float acc = 0.f;
#pragma unroll 8
    for (int h = h0; h < h0 + (H_ / 8); ++h) {
        acc += pooled[h] * W1[h * ADAPT_ + a];
    }
    __shared__ float part[8][ADAPT_];
    part[g][a] = acc;
    __syncthreads();

    if (tid < ADAPT_) {
        float s = b1[tid];
#pragma unroll
        for (int g2 = 0; g2 < 8; ++g2) s += part[g2][tid];
        g_hpre[b * ADAPT_ + tid] = s;
    }
}

// ---------------------------------------------------------------------------
// Threefry2x32 (JAX default PRNG), 20 rounds.
// ---------------------------------------------------------------------------
__device__ __forceinline__ uint32_t rotl32(uint32_t x, int d) {
    return (x << d) | (x >> (32 - d));
}

__device__ __forceinline__ uint2 threefry2x32(uint32_t k0, uint32_t k1,
                                              uint32_t x0, uint32_t x1) {
    const uint32_t k2 = k0 ^ k1 ^ 0x1BD11BDAu;
    const int R0[4] = {13, 15, 26, 6};
    const int R1[4] = {17, 29, 16, 24};
    x0 += k0; x1 += k1;
#pragma unroll
    for (int r = 0; r < 4; ++r) { x0 += x1; x1 = rotl32(x1, R0[r]); x1 ^= x0; }
    x0 += k1; x1 += k2 + 1u;
#pragma unroll
    for (int r = 0; r < 4; ++r) { x0 += x1; x1 = rotl32(x1, R1[r]); x1 ^= x0; }
    x0 += k2; x1 += k0 + 2u;
#pragma unroll
    for (int r = 0; r < 4; ++r) { x0 += x1; x1 = rotl32(x1, R0[r]); x1 ^= x0; }
    x0 += k0; x1 += k1 + 3u;
#pragma unroll
    for (int r = 0; r < 4; ++r) { x0 += x1; x1 = rotl32(x1, R1[r]); x1 ^= x0; }
    x0 += k1; x1 += k2 + 4u;
#pragma unroll
    for (int r = 0; r < 4; ++r) { x0 += x1; x1 = rotl32(x1, R0[r]); x1 ^= x0; }
    x0 += k2; x1 += k0 + 5u;
    return make_uint2(x0, x1);
}

// uniform [0,1) matching modern JAX (jax_threefry_partitionable=True):
// element i of the flat array uses 64-bit counter = i, i.e.
// (b1,b2) = threefry2x32(k0, k1, hi(i)=0, lo(i)=i); 32-bit draw = b1 ^ b2.
__device__ __forceinline__ float jax_uniform(uint32_t seed, uint32_t i) {
    uint2 r = threefry2x32(0u, seed, 0u, i);
    uint32_t bits = r.x ^ r.y;
    return __uint_as_float((bits >> 9) | 0x3F800000u) - 1.0f;
}

// ---------------------------------------------------------------------------
// Pass 3: LN + GELU + dropout + W2 + Gumbel top-k + softmax + EMA + entropy.
// Single block, 1024 threads (warp w = batch row b, lane = feature a).
// out layout: [mask 32*16][ema 16][entropy 1]
// ---------------------------------------------------------------------------
__global__ __launch_bounds__(1024) void pass3_head(const float* __restrict__ ln_g,
                                                   const float* __restrict__ ln_b,
                                                   const float* __restrict__ W2,
                                                   const float* __restrict__ b2,
                                                   const float* __restrict__ mask_logits,
                                                   const float* __restrict__ mask_ema,
                                                   float* __restrict__ out) {
    const int tid  = threadIdx.x;
    const int b    = tid >> 5;
    const int lane = tid & 31;

    float h = g_hpre[tid];

    // LayerNorm over 32 features (full warp)
    float m = h;
#pragma unroll
    for (int o = 16; o; o >>= 1) m += __shfl_xor_sync(0xFFFFFFFFu, m, o);
    m *= (1.0f / 32.0f);
    float d = h - m;
    float v = d * d;
#pragma unroll
    for (int o = 16; o; o >>= 1) v += __shfl_xor_sync(0xFFFFFFFFu, v, o);
    v *= (1.0f / 32.0f);
    h = d * rsqrtf(v + 1e-5f) * ln_g[lane] + ln_b[lane];

    // exact GELU
    h = 0.5f * h * (1.0f + erff(h * 0.70710678118654752f));

    // Dropout(0.1), training=True, key(1), shape (32,32), flat index = tid
    {
        float u = jax_uniform(1u, (uint32_t)tid);
        h = (u >= 0.1f) ? h * (1.0f / 0.9f) : 0.0f;
    }

    __shared__ float hsm[B_][ADAPT_];
    hsm[b][lane] = h;
    __syncthreads();

    __shared__ float comb[B_][RANK_];
    __shared__ float pert[B_][RANK_];
    __shared__ float maskv[B_][RANK_];

    if (lane < RANK_) {
        const int j = lane;
        float acc = b2[j] + mask_logits[j];
#pragma unroll
        for (int a = 0; a < ADAPT_; ++a) acc += hsm[b][a] * W2[a * RANK_ + j];
        comb[b][j] = acc;

        // Gumbel noise, key(2), shape (32,16), flat index b*16+j
        float u = jax_uniform(2u, (uint32_t)(b * RANK_ + j));
        float gmb = -logf(-logf(u + 1e-8f) + 1e-8f);
        pert[b][j] = acc + gmb;
    }
    __syncwarp();

    if (lane < RANK_) {
        const int j = lane;
        const float vj = pert[b][j];
        int rank = 0;
#pragma unroll
        for (int m2 = 0; m2 < RANK_; ++m2) {
            float vm = pert[b][m2];
            rank += (vm > vj) || (vm == vj && m2 < j);
        }
        float khot = (rank < K_) ? 1.0f : 0.0f;

        // softmax(combined / TEMP) with max subtraction (TEMP = 0.1)
        float mx = -1e30f;
#pragma unroll
        for (int m2 = 0; m2 < RANK_; ++m2) mx = fmaxf(mx, comb[b][m2]);
        float e = expf((comb[b][j] - mx) * 10.0f);
        float ssum = 0.0f;
#pragma unroll
        for (int m2 = 0; m2 < RANK_; ++m2) ssum += expf((comb[b][m2] - mx) * 10.0f);
        float soft = e / ssum;

        // straight-through forward value
        float mv = (khot + soft) - soft;
        maskv[b][j] = mv;
        out[b * RANK_ + j] = mv;
    }
    __syncthreads();

    if (tid < RANK_) {
        float s = 0.0f;
#pragma unroll
        for (int bb = 0; bb < B_; ++bb) s += maskv[bb][tid];
        float ema = 0.99f * mask_ema[tid] + 0.01f * (s * (1.0f / (float)B_));
        out[B_ * RANK_ + tid] = ema;

        __shared__ float esm[RANK_];
        esm[tid] = ema * logf(ema + 1e-8f);
        __syncwarp(0x0000FFFFu);
        if (tid == 0) {
            float tot = 0.0f;
#pragma unroll
            for (int j = 0; j < RANK_; ++j) tot += esm[j];
            out[B_ * RANK_ + RANK_] = -tot;
        }
    }
}

// ---------------------------------------------------------------------------
extern "C" void kernel_launch(void* const* d_in, const int* in_sizes, int n_in,
                              void* d_out, int out_size) {
    const float* hidden      = (const float*)d_in[0];
    const float* W1          = (const float*)d_in[1];
    const float* b1          = (const float*)d_in[2];
    const float* ln_g        = (const float*)d_in[3];
    const float* ln_b        = (const float*)d_in[4];
    const float* W2          = (const float*)d_in[5];
    const float* b2          = (const float*)d_in[6];
    const float* mask_logits = (const float*)d_in[7];
    const float* mask_ema    = (const float*)d_in[8];
    float* out = (float*)d_out;

    dim3 g1(SSPLIT, B_);
    pass1_partial_sums<<<g1, 512>>>(hidden);
    pass2_pool_proj<<<B_, 256>>>(W1, b1);
    pass3_head<<<1, 1024>>>(ln_g, ln_b, W2, b2, mask_logits, mask_ema, out);
}

// round 3
// speedup vs baseline: 1.0968x; 1.0968x over previous
#include <cuda_runtime.h>
#include <stdint.h>

// Shapes (fixed by the problem)
#define B_  32
#define S_  4096
#define H_  2048
#define ADAPT_ 32
#define RANK_ 16
#define K_ 8

#define CSPLIT 64          // column chunks of 32 floats each (64*32 = 2048 = H)
#define CHUNK_COLS 32

// Static scratch (no allocations allowed): partial projections [CSPLIT][B][ADAPT]
__device__ float g_part[CSPLIT * B_ * ADAPT_];   // 256 KB

// ---------------------------------------------------------------------------
// K1: for block (cs, b): sum columns [cs*32, cs*32+32) of x[b] over all S rows,
// then fold through W1 rows [cs*32, cs*32+32) -> partial proj[32].
// grid (CSPLIT, B_), block 256. Thread (ty=t>>3, tx=t&7) owns float4 column tx,
// rows ty, ty+32, ... (128 iterations).
// ---------------------------------------------------------------------------
__global__ __launch_bounds__(256) void k1_colsum_proj(const float* __restrict__ x,
                                                      const float* __restrict__ W1) {
    const int cs = blockIdx.x;
    const int b  = blockIdx.y;
    const int tx = threadIdx.x & 7;   // float4 index within 32-col chunk
    const int ty = threadIdx.x >> 3;  // 0..31 row group

    const int c0 = cs * CHUNK_COLS;   // first float column of this chunk
    const float4* p = reinterpret_cast<const float4*>(x)
                    + (size_t)b * S_ * (H_ / 4) + (c0 >> 2) + tx;

    float ax = 0.f, ay = 0.f, az = 0.f, aw = 0.f;
#pragma unroll 8
    for (int i = 0; i < S_ / 32; ++i) {
        float4 v = p[(size_t)(ty + 32 * i) * (H_ / 4)];
        ax += v.x; ay += v.y; az += v.z; aw += v.w;
    }

    __shared__ float sm[32][33];      // [ty][col-within-chunk], padded
    sm[ty][4 * tx + 0] = ax;
    sm[ty][4 * tx + 1] = ay;
    sm[ty][4 * tx + 2] = az;
    sm[ty][4 * tx + 3] = aw;
    __syncthreads();

    __shared__ float colsum[CHUNK_COLS];
    if (threadIdx.x < 32) {
        const int c = threadIdx.x;
        float s = 0.f;
#pragma unroll
        for (int t = 0; t < 32; ++t) s += sm[t][c];
        colsum[c] = s;
    }
    __syncwarp();

    if (threadIdx.x < 32) {
        const int a = threadIdx.x;
        float acc = 0.f;
#pragma unroll
        for (int c = 0; c < CHUNK_COLS; ++c) {
            acc += colsum[c] * W1[(size_t)(c0 + c) * ADAPT_ + a];
        }
        g_part[(cs * B_ + b) * ADAPT_ + a] = acc;
    }
}

// ---------------------------------------------------------------------------
// Threefry2x32 (JAX default PRNG), 20 rounds.
// ---------------------------------------------------------------------------
__device__ __forceinline__ uint32_t rotl32(uint32_t x, int d) {
    return (x << d) | (x >> (32 - d));
}

__device__ __forceinline__ uint2 threefry2x32(uint32_t k0, uint32_t k1,
                                              uint32_t x0, uint32_t x1) {
    const uint32_t k2 = k0 ^ k1 ^ 0x1BD11BDAu;
    const int R0[4] = {13, 15, 26, 6};
    const int R1[4] = {17, 29, 16, 24};
    x0 += k0; x1 += k1;
#pragma unroll
    for (int r = 0; r < 4; ++r) { x0 += x1; x1 = rotl32(x1, R0[r]); x1 ^= x0; }
    x0 += k1; x1 += k2 + 1u;
#pragma unroll
    for (int r = 0; r < 4; ++r) { x0 += x1; x1 = rotl32(x1, R1[r]); x1 ^= x0; }
    x0 += k2; x1 += k0 + 2u;
#pragma unroll
    for (int r = 0; r < 4; ++r) { x0 += x1; x1 = rotl32(x1, R0[r]); x1 ^= x0; }
    x0 += k0; x1 += k1 + 3u;
#pragma unroll
    for (int r = 0; r < 4; ++r) { x0 += x1; x1 = rotl32(x1, R1[r]); x1 ^= x0; }
    x0 += k1; x1 += k2 + 4u;
#pragma unroll
    for (int r = 0; r < 4; ++r) { x0 += x1; x1 = rotl32(x1, R0[r]); x1 ^= x0; }
    x0 += k2; x1 += k0 + 5u;
    return make_uint2(x0, x1);
}

// uniform [0,1) matching modern JAX (jax_threefry_partitionable=True):
// element i uses 64-bit counter = i; 32-bit draw = x0 ^ x1.
__device__ __forceinline__ float jax_uniform(uint32_t seed, uint32_t i) {
    uint2 r = threefry2x32(0u, seed, 0u, i);
    uint32_t bits = r.x ^ r.y;
    return __uint_as_float((bits >> 9) | 0x3F800000u) - 1.0f;
}

// ---------------------------------------------------------------------------
// K2: reduce partial projections -> hpre, then LN + GELU + dropout + W2 +
// Gumbel top-k + softmax + EMA + entropy. Single block, 1024 threads
// (warp w = batch row b, lane = feature a).
// out layout: [mask 32*16][ema 16][entropy 1]
// ---------------------------------------------------------------------------
__global__ __launch_bounds__(1024) void k2_head(const float* __restrict__ b1,
                                                const float* __restrict__ ln_g,
                                                const float* __restrict__ ln_b,
                                                const float* __restrict__ W2,
                                                const float* __restrict__ b2,
                                                const float* __restrict__ mask_logits,
                                                const float* __restrict__ mask_ema,
                                                float* __restrict__ out) {
    const int tid  = threadIdx.x;
    const int b    = tid >> 5;
    const int lane = tid & 31;

    // hpre[b][a] = (1/S) * sum_k g_part[k][b][a] + b1[a]
    float acc = 0.f;
#pragma unroll 8
    for (int k = 0; k < CSPLIT; ++k) {
        acc += g_part[(k * B_ + b) * ADAPT_ + lane];
    }
    float h = acc * (1.0f / (float)S_) + b1[lane];

    // LayerNorm over 32 features (full warp)
    float m = h;
#pragma unroll
    for (int o = 16; o; o >>= 1) m += __shfl_xor_sync(0xFFFFFFFFu, m, o);
    m *= (1.0f / 32.0f);
    float d = h - m;
    float v = d * d;
#pragma unroll
    for (int o = 16; o; o >>= 1) v += __shfl_xor_sync(0xFFFFFFFFu, v, o);
    v *= (1.0f / 32.0f);
    h = d * rsqrtf(v + 1e-5f) * ln_g[lane] + ln_b[lane];

    // exact GELU
    h = 0.5f * h * (1.0f + erff(h * 0.70710678118654752f));

    // Dropout(0.1), training=True, key(1), shape (32,32), flat index = tid
    {
        float u = jax_uniform(1u, (uint32_t)tid);
        h = (u >= 0.1f) ? h * (1.0f / 0.9f) : 0.0f;
    }

    __shared__ float hsm[B_][ADAPT_];
    hsm[b][lane] = h;
    __syncthreads();

    __shared__ float comb[B_][RANK_];
    __shared__ float pert[B_][RANK_];
    __shared__ float maskv[B_][RANK_];

    if (lane < RANK_) {
        const int j = lane;
        float acc2 = b2[j] + mask_logits[j];
#pragma unroll
        for (int a = 0; a < ADAPT_; ++a) acc2 += hsm[b][a] * W2[a * RANK_ + j];
        comb[b][j] = acc2;

        // Gumbel noise, key(2), shape (32,16), flat index b*16+j
        float u = jax_uniform(2u, (uint32_t)(b * RANK_ + j));
        float gmb = -logf(-logf(u + 1e-8f) + 1e-8f);
        pert[b][j] = acc2 + gmb;
    }
    __syncwarp();

    if (lane < RANK_) {
        const int j = lane;
        const float vj = pert[b][j];
        int rank = 0;
#pragma unroll
        for (int m2 = 0; m2 < RANK_; ++m2) {
            float vm = pert[b][m2];
            rank += (vm > vj) || (vm == vj && m2 < j);
        }
        float khot = (rank < K_) ? 1.0f : 0.0f;

        // softmax(combined / TEMP), TEMP = 0.1
        float mx = -1e30f;
#pragma unroll
        for (int m2 = 0; m2 < RANK_; ++m2) mx = fmaxf(mx, comb[b][m2]);
        float e = expf((comb[b][j] - mx) * 10.0f);
        float ssum = 0.0f;
#pragma unroll
        for (int m2 = 0; m2 < RANK_; ++m2) ssum += expf((comb[b][m2] - mx) * 10.0f);
        float soft = e / ssum;

        // straight-through forward value
        float mv = (khot + soft) - soft;
        maskv[b][j] = mv;
        out[b * RANK_ + j] = mv;
    }
    __syncthreads();

    if (tid < RANK_) {
        float s = 0.0f;
#pragma unroll
        for (int bb = 0; bb < B_; ++bb) s += maskv[bb][tid];
        float ema = 0.99f * mask_ema[tid] + 0.01f * (s * (1.0f / (float)B_));
        out[B_ * RANK_ + tid] = ema;

        __shared__ float esm[RANK_];
        esm[tid] = ema * logf(ema + 1e-8f);
        __syncwarp(0x0000FFFFu);
        if (tid == 0) {
            float tot = 0.0f;
#pragma unroll
            for (int j = 0; j < RANK_; ++j) tot += esm[j];
            out[B_ * RANK_ + RANK_] = -tot;
        }
    }
}

// ---------------------------------------------------------------------------
extern "C" void kernel_launch(void* const* d_in, const int* in_sizes, int n_in,
                              void* d_out, int out_size) {
    const float* hidden      = (const float*)d_in[0];
    const float* W1          = (const float*)d_in[1];
    const float* b1          = (const float*)d_in[2];
    const float* ln_g        = (const float*)d_in[3];
    const float* ln_b        = (const float*)d_in[4];
    const float* W2          = (const float*)d_in[5];
    const float* b2          = (const float*)d_in[6];
    const float* mask_logits = (const float*)d_in[7];
    const float* mask_ema    = (const float*)d_in[8];
    float* out = (float*)d_out;

    dim3 g1(CSPLIT, B_);
    k1_colsum_proj<<<g1, 256>>>(hidden, W1);
    k2_head<<<1, 1024>>>(b1, ln_g, ln_b, W2, b2, mask_logits, mask_ema, out);
}

// round 4
// speedup vs baseline: 1.1476x; 1.0464x over previous
#include <cuda_runtime.h>
#include <stdint.h>

// Shapes (fixed by the problem)
#define B_  32
#define S_  4096
#define H_  2048
#define ADAPT_ 32
#define RANK_ 16
#define K_ 8

#define CSPLIT 64                    // column chunks of 32 floats each
#define CHUNK_COLS 32
#define TOTAL_BLOCKS (CSPLIT * B_)   // 2048

// Static scratch: partial projections, layout [b][cs][a] (contiguous per batch)
__device__ float g_part[B_ * CSPLIT * ADAPT_];   // 256 KB
__device__ unsigned g_count = 0;                 // completion counter (self-resetting)

// ---------------------------------------------------------------------------
// Threefry2x32 (JAX default PRNG), 20 rounds.
// ---------------------------------------------------------------------------
__device__ __forceinline__ uint32_t rotl32(uint32_t x, int d) {
    return (x << d) | (x >> (32 - d));
}

__device__ __forceinline__ uint2 threefry2x32(uint32_t k0, uint32_t k1,
                                              uint32_t x0, uint32_t x1) {
    const uint32_t k2 = k0 ^ k1 ^ 0x1BD11BDAu;
    const int R0[4] = {13, 15, 26, 6};
    const int R1[4] = {17, 29, 16, 24};
    x0 += k0; x1 += k1;
#pragma unroll
    for (int r = 0; r < 4; ++r) { x0 += x1; x1 = rotl32(x1, R0[r]); x1 ^= x0; }
    x0 += k1; x1 += k2 + 1u;
#pragma unroll
    for (int r = 0; r < 4; ++r) { x0 += x1; x1 = rotl32(x1, R1[r]); x1 ^= x0; }
    x0 += k2; x1 += k0 + 2u;
#pragma unroll
    for (int r = 0; r < 4; ++r) { x0 += x1; x1 = rotl32(x1, R0[r]); x1 ^= x0; }
    x0 += k0; x1 += k1 + 3u;
#pragma unroll
    for (int r = 0; r < 4; ++r) { x0 += x1; x1 = rotl32(x1, R1[r]); x1 ^= x0; }
    x0 += k1; x1 += k2 + 4u;
#pragma unroll
    for (int r = 0; r < 4; ++r) { x0 += x1; x1 = rotl32(x1, R0[r]); x1 ^= x0; }
    x0 += k2; x1 += k0 + 5u;
    return make_uint2(x0, x1);
}

// uniform [0,1) matching modern JAX (jax_threefry_partitionable=True):
// element i uses 64-bit counter = i; 32-bit draw = x0 ^ x1.
__device__ __forceinline__ float jax_uniform(uint32_t seed, uint32_t i) {
    uint2 r = threefry2x32(0u, seed, 0u, i);
    uint32_t bits = r.x ^ r.y;
    return __uint_as_float((bits >> 9) | 0x3F800000u) - 1.0f;
}

// ---------------------------------------------------------------------------
// Fused kernel: grid (CSPLIT, B_), 256 threads.
// Stage 1 (all blocks): column-sum chunk of 32 cols over all S rows, fold
// through W1 rows -> g_part[b][cs][32].
// Stage 2 (last block only): reduce partials -> LN -> GELU -> dropout -> W2
// -> Gumbel top-k -> softmax -> mask/EMA/entropy.
// out layout: [mask 32*16][ema 16][entropy 1]
// ---------------------------------------------------------------------------
__global__ __launch_bounds__(256) void k_fused(const float* __restrict__ x,
                                               const float* __restrict__ W1,
                                               const float* __restrict__ b1,
                                               const float* __restrict__ ln_g,
                                               const float* __restrict__ ln_b,
                                               const float* __restrict__ W2,
                                               const float* __restrict__ b2,
                                               const float* __restrict__ mask_logits,
                                               const float* __restrict__ mask_ema,
                                               float* __restrict__ out) {
    const int cs = blockIdx.x;
    const int b  = blockIdx.y;
    const int t  = threadIdx.x;

    // ---------------- Stage 1: streaming column sums ----------------
    {
        const int tx = t & 7;    // float4 index within 32-col chunk
        const int ty = t >> 3;   // 0..31 row group
        const int c0 = cs * CHUNK_COLS;

        const float4* p = reinterpret_cast<const float4*>(x)
                        + (size_t)b * S_ * (H_ / 4) + (c0 >> 2) + tx;

        float ax = 0.f, ay = 0.f, az = 0.f, aw = 0.f;
#pragma unroll 8
        for (int i = 0; i < S_ / 32; ++i) {
            float4 v = p[(size_t)(ty + 32 * i) * (H_ / 4)];
            ax += v.x; ay += v.y; az += v.z; aw += v.w;
        }

        __shared__ float sm[32][33];
        sm[ty][4 * tx + 0] = ax;
        sm[ty][4 * tx + 1] = ay;
        sm[ty][4 * tx + 2] = az;
        sm[ty][4 * tx + 3] = aw;
        __syncthreads();

        __shared__ float colsum[CHUNK_COLS];
        if (t < 32) {
            float s = 0.f;
#pragma unroll
            for (int r = 0; r < 32; ++r) s += sm[r][t];
            colsum[t] = s;
        }
        __syncwarp();

        if (t < 32) {
            const int a = t;
            float acc = 0.f;
#pragma unroll
            for (int c = 0; c < CHUNK_COLS; ++c) {
                acc += colsum[c] * W1[(size_t)(c0 + c) * ADAPT_ + a];
            }
            g_part[(b * CSPLIT + cs) * ADAPT_ + a] = acc;
        }
    }

    // ---------------- Completion detection ----------------
    __threadfence();
    __shared__ unsigned is_last;
    if (t == 0) {
        unsigned old = atomicAdd(&g_count, 1u);
        is_last = (old == TOTAL_BLOCKS - 1u) ? 1u : 0u;
    }
    __syncthreads();
    if (!is_last) return;
    if (t == 0) g_count = 0;          // reset for next graph replay
    __threadfence();                  // acquire-side safety before reading g_part

    // ---------------- Stage 2: tail (single block, 256 threads) ----------------
    const int lane = t & 31;
    const int w    = t >> 5;

    __shared__ float hsm[B_][ADAPT_];

    // A: reduce partials -> hpre. Thread (bA = t>>3, a4 = t&7) owns 4 features.
    {
        const int bA = t >> 3;
        const int a4 = t & 7;
        const float4* gp = reinterpret_cast<const float4*>(g_part);
        float ax = 0.f, ay = 0.f, az = 0.f, aw = 0.f;
#pragma unroll 8
        for (int k = 0; k < CSPLIT; ++k) {
            float4 v = gp[(bA * CSPLIT + k) * (ADAPT_ / 4) + a4];
            ax += v.x; ay += v.y; az += v.z; aw += v.w;
        }
        const float invS = 1.0f / (float)S_;
        hsm[bA][4 * a4 + 0] = ax * invS + b1[4 * a4 + 0];
        hsm[bA][4 * a4 + 1] = ay * invS + b1[4 * a4 + 1];
        hsm[bA][4 * a4 + 2] = az * invS + b1[4 * a4 + 2];
        hsm[bA][4 * a4 + 3] = aw * invS + b1[4 * a4 + 3];
    }
    __syncthreads();

    // B: LN + GELU + dropout. Warp w handles batch rows 4w..4w+3.
#pragma unroll
    for (int bb = 0; bb < 4; ++bb) {
        const int bL = 4 * w + bb;
        float h = hsm[bL][lane];

        float m = h;
#pragma unroll
        for (int o = 16; o; o >>= 1) m += __shfl_xor_sync(0xFFFFFFFFu, m, o);
        m *= (1.0f / 32.0f);
        float d = h - m;
        float v = d * d;
#pragma unroll
        for (int o = 16; o; o >>= 1) v += __shfl_xor_sync(0xFFFFFFFFu, v, o);
        v *= (1.0f / 32.0f);
        h = d * rsqrtf(v + 1e-5f) * ln_g[lane] + ln_b[lane];

        // exact GELU
        h = 0.5f * h * (1.0f + erff(h * 0.70710678118654752f));

        // Dropout(0.1), key(1), shape (32,32), flat index bL*32+lane
        float u = jax_uniform(1u, (uint32_t)(bL * ADAPT_ + lane));
        h = (u >= 0.1f) ? h * (1.0f / 0.9f) : 0.0f;

        hsm[bL][lane] = h;
    }
    __syncthreads();

    // C: logits + Gumbel. Thread (bC = t>>3, jj = t&7) handles j = jj, jj+8.
    __shared__ float comb[B_][RANK_];
    __shared__ float pert[B_][RANK_];
    {
        const int bC = t >> 3;
        const int jj = t & 7;
#pragma unroll
        for (int r = 0; r < 2; ++r) {
            const int j = jj + 8 * r;
            float acc = b2[j] + mask_logits[j];
#pragma unroll
            for (int a = 0; a < ADAPT_; ++a) acc += hsm[bC][a] * W2[a * RANK_ + j];
            comb[bC][j] = acc;

            float u = jax_uniform(2u, (uint32_t)(bC * RANK_ + j));
            float gmb = -logf(-logf(u + 1e-8f) + 1e-8f);
            pert[bC][j] = acc + gmb;
        }
    }
    __syncthreads();

    // D: top-k rank, softmax, straight-through mask.
    __shared__ float maskv[B_][RANK_];
    {
        const int bC = t >> 3;
        const int jj = t & 7;

        float mx = -1e30f;
#pragma unroll
        for (int m2 = 0; m2 < RANK_; ++m2) mx = fmaxf(mx, comb[bC][m2]);
        float ssum = 0.0f;
#pragma unroll
        for (int m2 = 0; m2 < RANK_; ++m2) ssum += expf((comb[bC][m2] - mx) * 10.0f);

#pragma unroll
        for (int r = 0; r < 2; ++r) {
            const int j = jj + 8 * r;
            const float vj = pert[bC][j];
            int rank = 0;
#pragma unroll
            for (int m2 = 0; m2 < RANK_; ++m2) {
                float vm = pert[bC][m2];
                rank += (vm > vj) || (vm == vj && m2 < j);
            }
            float khot = (rank < K_) ? 1.0f : 0.0f;
            float soft = expf((comb[bC][j] - mx) * 10.0f) / ssum;

            float mv = (khot + soft) - soft;   // straight-through forward
            maskv[bC][j] = mv;
            out[bC * RANK_ + j] = mv;
        }
    }
    __syncthreads();

    // E: EMA + entropy (threads 0..15, all in warp 0).
    if (t < RANK_) {
        float s = 0.0f;
#pragma unroll
        for (int bb = 0; bb < B_; ++bb) s += maskv[bb][t];
        float ema = 0.99f * mask_ema[t] + 0.01f * (s * (1.0f / (float)B_));
        out[B_ * RANK_ + t] = ema;

        __shared__ float esm[RANK_];
        esm[t] = ema * logf(ema + 1e-8f);
        __syncwarp(0x0000FFFFu);
        if (t == 0) {
            float tot = 0.0f;
#pragma unroll
            for (int j = 0; j < RANK_; ++j) tot += esm[j];
            out[B_ * RANK_ + RANK_] = -tot;
        }
    }
}

// ---------------------------------------------------------------------------
extern "C" void kernel_launch(void* const* d_in, const int* in_sizes, int n_in,
                              void* d_out, int out_size) {
    const float* hidden      = (const float*)d_in[0];
    const float* W1          = (const float*)d_in[1];
    const float* b1          = (const float*)d_in[2];
    const float* ln_g        = (const float*)d_in[3];
    const float* ln_b        = (const float*)d_in[4];
    const float* W2          = (const float*)d_in[5];
    const float* b2          = (const float*)d_in[6];
    const float* mask_logits = (const float*)d_in[7];
    const float* mask_ema    = (const float*)d_in[8];
    float* out = (float*)d_out;

    dim3 g1(CSPLIT, B_);
    k_fused<<<g1, 256>>>(hidden, W1, b1, ln_g, ln_b, W2, b2,
                         mask_logits, mask_ema, out);
}